// round 13
// baseline (speedup 1.0000x reference)
#include <cuda_runtime.h>
#include <cstdint>

#define Df 640
#define Cc 64
#define Nn 1024
#define Qq 2048
#define NB 10
typedef unsigned long long u64t;

__device__ __align__(16) float g_sigma[(size_t)Cc * Df * Df];
__device__ __align__(16) float g_colbuf[(size_t)Cc * NB * 4096];
__device__ __align__(16) float g_rowbuf[(size_t)Cc * NB * 4096];
__device__ __align__(16) float g_pinv[(size_t)Cc * 4096];
__device__ __align__(16) float g_LLt[Df * Df];
__device__ __align__(16) float g_mu[Cc * Df];
__device__ int g_cnt[Cc];
__device__ int g_idx[Cc * Nn];

// ---------------- LLt = L @ L^T (verified) ----------------
__global__ void k_llt(const float* __restrict__ td, const float* __restrict__ tl) {
    __shared__ float Li[32][33], Lj[32][33];
    int i0 = blockIdx.x * 32, j0 = blockIdx.y * 32;
    int tx = threadIdx.x, ty = threadIdx.y;
    float acc = 0.f;
    for (int k0 = 0; k0 < Df; k0 += 32) {
        int k = k0 + tx, r = i0 + ty;
        Li[ty][tx] = (r == k) ? fabsf(td[r]) : ((r > k) ? tl[r * Df + k] : 0.f);
        r = j0 + ty;
        Lj[ty][tx] = (r == k) ? fabsf(td[r]) : ((r > k) ? tl[r * Df + k] : 0.f);
        __syncthreads();
#pragma unroll
        for (int kk = 0; kk < 32; kk++) acc += Li[ty][kk] * Lj[tx][kk];
        __syncthreads();
    }
    g_LLt[(i0 + ty) * Df + (j0 + tx)] = acc;
}

__global__ void k_classidx(const int* __restrict__ y) {
    __shared__ int ys[Nn];
    int c = blockIdx.x;
    for (int n = threadIdx.x; n < Nn; n += blockDim.x) ys[n] = y[n];
    __syncthreads();
    if (threadIdx.x == 0) {
        int cnt = 0;
        for (int n = 0; n < Nn; n++) if (ys[n] == c) g_idx[c * Nn + (cnt++)] = n;
        g_cnt[c] = cnt;
    }
}

__global__ void k_mu(const float* __restrict__ X, const float* __restrict__ m,
                     const float* __restrict__ kappa) {
    int c = blockIdx.x, cnt = g_cnt[c];
    float Nc = (float)cnt, kap = fabsf(kappa[0]) + 1e-6f, w = Nc / (kap + Nc);
    for (int d = threadIdx.x; d < Df; d += blockDim.x) {
        float s = 0.f;
        for (int k = 0; k < cnt; k++) s += X[(size_t)g_idx[c * Nn + k] * Df + d];
        g_mu[c * Df + d] = (1.f - w) * m[d] + w * (s / Nc);
    }
}

// ---------------- sigma build (verified) ----------------
__global__ void __launch_bounds__(256) k_sigma(const float* __restrict__ X,
                                               const float* __restrict__ m,
                                               const float* __restrict__ kappa,
                                               const float* __restrict__ nu) {
    __shared__ float Xi[16][66], Xj[16][66];
    __shared__ int sidx[16];
    int c = blockIdx.z, Ib = blockIdx.y * 64, Jb = blockIdx.x * 64;
    int tid = threadIdx.x, tx = tid & 7, ty = tid >> 3;
    int cnt = g_cnt[c];
    float acc[2][8] = {};
    for (int k0 = 0; k0 < cnt; k0 += 16) {
        int nl = min(16, cnt - k0);
        if (tid < 16) sidx[tid] = (tid < nl) ? g_idx[c * Nn + k0 + tid] : 0;
        __syncthreads();
        for (int idx = tid; idx < 16 * 64; idx += 256) {
            int s = idx >> 6, col = idx & 63;
            float vi = 0.f, vj = 0.f;
            if (s < nl) {
                const float* xr = X + (size_t)sidx[s] * Df;
                vi = xr[Ib + col]; vj = xr[Jb + col];
            }
            Xi[s][col] = vi; Xj[s][col] = vj;
        }
        __syncthreads();
#pragma unroll
        for (int t = 0; t < 16; t++) {
            float a0 = Xi[t][ty * 2], a1 = Xi[t][ty * 2 + 1];
            const float* bj = &Xj[t][tx * 8];
#pragma unroll
            for (int k = 0; k < 8; k++) {
                float b = bj[k];
                acc[0][k] += a0 * b;
                acc[1][k] += a1 * b;
            }
        }
        __syncthreads();
    }
    float kap = fabsf(kappa[0]) + 1e-6f;
    float nu_ = fmaxf(nu[0], (float)(Df - 1) + 1e-6f);
    float Nc = (float)cnt;
    float inv_denom = 1.f / (nu_ + Nc + (float)Df + 2.f);
    float kpn = kap + Nc;
#pragma unroll
    for (int r = 0; r < 2; r++) {
        int i = Ib + ty * 2 + r;
        float mi = m[i], mui = g_mu[c * Df + i];
        float* dst = g_sigma + (size_t)c * Df * Df + (size_t)i * Df + Jb + tx * 8;
        const float* llt = g_LLt + (size_t)i * Df + Jb + tx * 8;
#pragma unroll
        for (int k = 0; k < 8; k++) {
            int j = Jb + tx * 8 + k;
            float v = llt[k] + acc[r][k] + kap * mi * m[j] - kpn * mui * g_mu[c * Df + j];
            dst[k] = v * inv_denom;
        }
    }
}

// ---------------- sweep step A: save panels (verified R10) ----------------
__global__ void __launch_bounds__(256) k_savepanel(int kb) {
    int b = blockIdx.x, c = blockIdx.y;
    if (b == kb) return;
    const float* M = g_sigma + (size_t)c * Df * Df;
    float* dst = g_colbuf + ((size_t)c * NB + b) * 4096;
    int tid = threadIdx.x;
    if (b > kb) {
        for (int idx = tid; idx < 4096; idx += 256) {
            int t = idx >> 6, a = idx & 63;
            dst[idx] = M[(size_t)(kb * 64 + t) * Df + b * 64 + a];
        }
    } else {
        __shared__ float Ts[64][65];
        for (int idx = tid; idx < 4096; idx += 256) {
            int a = idx >> 6, t = idx & 63;
            Ts[a][t] = M[(size_t)(b * 64 + a) * Df + kb * 64 + t];
        }
        __syncthreads();
        for (int idx = tid; idx < 4096; idx += 256) {
            int t = idx >> 6, a = idx & 63;
            dst[idx] = Ts[a][t];
        }
    }
}

// ---------------- sweep step B: invert pivot (verified R10) ----------------
__global__ void __launch_bounds__(256) k_pinv(int kb) {
    __shared__ float Psm[64 * 65];
    __shared__ float colv[64];
    int c = blockIdx.x, tid = threadIdx.x, K0 = kb * 64;
    const float* M = g_sigma + (size_t)c * Df * Df;
    for (int idx = tid; idx < 4096; idx += 256)
        Psm[(idx >> 6) * 65 + (idx & 63)] = M[(size_t)(K0 + (idx >> 6)) * Df + K0 + (idx & 63)];
    __syncthreads();
    for (int t = 0; t < 64; t++) {
        if (tid < 64) colv[tid] = Psm[tid * 65 + t];
        __syncthreads();
        float invp = 1.f / colv[t];
        if (tid < 64) {
            float v = Psm[t * 65 + tid];
            Psm[t * 65 + tid] = (tid == t) ? invp : v * invp;
        }
        __syncthreads();
        for (int idx = tid; idx < 4096; idx += 256) {
            int i = idx >> 6, j = idx & 63;
            if (i != t) {
                float base = (j == t) ? 0.f : Psm[i * 65 + j];
                Psm[i * 65 + j] = base - colv[i] * Psm[t * 65 + j];
            }
        }
        __syncthreads();
    }
    for (int idx = tid; idx < 4096; idx += 256)
        g_pinv[(size_t)c * 4096 + idx] = Psm[(idx >> 6) * 65 + (idx & 63)];
}

// ---------------- sweep step C: rowpanel (verified R10) ----------------
__global__ void __launch_bounds__(256) k_rowpanel(int kb) {
    int j = blockIdx.x, c = blockIdx.y;
    int tid = threadIdx.x, K0 = kb * 64;
    float* M = g_sigma + (size_t)c * Df * Df;
    const float* Pv = g_pinv + (size_t)c * 4096;
    if (j == kb) {
        for (int idx = tid; idx < 4096; idx += 256)
            M[(size_t)(K0 + (idx >> 6)) * Df + K0 + (idx & 63)] = -Pv[idx];
        return;
    }
    __shared__ float Ps[64][65];
    __shared__ __align__(16) float Rs[64][68];
    for (int idx = tid; idx < 4096; idx += 256) {
        Ps[idx >> 6][idx & 63] = Pv[idx];
        Rs[idx >> 6][idx & 63] = g_colbuf[((size_t)c * NB + j) * 4096 + idx];
    }
    __syncthreads();
    int tx = tid & 15, ty = tid >> 4;
    float acc[4][4] = {};
#pragma unroll 8
    for (int t = 0; t < 64; t++) {
        float a0 = Ps[ty * 4 + 0][t], a1 = Ps[ty * 4 + 1][t];
        float a2 = Ps[ty * 4 + 2][t], a3 = Ps[ty * 4 + 3][t];
        float4 b = *(const float4*)&Rs[t][tx * 4];
        acc[0][0] += a0 * b.x; acc[0][1] += a0 * b.y; acc[0][2] += a0 * b.z; acc[0][3] += a0 * b.w;
        acc[1][0] += a1 * b.x; acc[1][1] += a1 * b.y; acc[1][2] += a1 * b.z; acc[1][3] += a1 * b.w;
        acc[2][0] += a2 * b.x; acc[2][1] += a2 * b.y; acc[2][2] += a2 * b.z; acc[2][3] += a2 * b.w;
        acc[3][0] += a3 * b.x; acc[3][1] += a3 * b.y; acc[3][2] += a3 * b.z; acc[3][3] += a3 * b.w;
    }
    float* rb = g_rowbuf + ((size_t)c * NB + j) * 4096;
#pragma unroll
    for (int r = 0; r < 4; r++)
        *(float4*)&rb[(ty * 4 + r) * 64 + tx * 4] =
            make_float4(acc[r][0], acc[r][1], acc[r][2], acc[r][3]);
    if (j > kb) {
#pragma unroll
        for (int r = 0; r < 4; r++)
            *(float4*)&M[(size_t)(K0 + ty * 4 + r) * Df + j * 64 + tx * 4] =
                make_float4(acc[r][0], acc[r][1], acc[r][2], acc[r][3]);
    } else {
        __syncthreads();
#pragma unroll
        for (int r = 0; r < 4; r++) {
            Ps[ty * 4 + r][tx * 4 + 0] = acc[r][0];
            Ps[ty * 4 + r][tx * 4 + 1] = acc[r][1];
            Ps[ty * 4 + r][tx * 4 + 2] = acc[r][2];
            Ps[ty * 4 + r][tx * 4 + 3] = acc[r][3];
        }
        __syncthreads();
        for (int idx = tid; idx < 4096; idx += 256) {
            int x = idx >> 6, yv = idx & 63;
            M[(size_t)(j * 64 + x) * Df + K0 + yv] = Ps[yv][x];
        }
    }
}

// ---------------- sweep step D: rank-64 update upper tiles (verified R10) ----------------
__global__ void __launch_bounds__(256) k_update(int kb) {
    int j = blockIdx.x, i = blockIdx.y, c = blockIdx.z;
    if (i > j || i == kb || j == kb) return;
    __shared__ float As[64][65];
    __shared__ __align__(16) float Bs[64][68];
    int tid = threadIdx.x;
    const float* ca = g_colbuf + ((size_t)c * NB + i) * 4096;
    const float* rb = g_rowbuf + ((size_t)c * NB + j) * 4096;
    for (int idx = tid; idx < 4096; idx += 256) {
        As[idx >> 6][idx & 63] = ca[idx];
        Bs[idx >> 6][idx & 63] = rb[idx];
    }
    __syncthreads();
    float* M = g_sigma + (size_t)c * Df * Df;
    int tx = tid & 15, ty = tid >> 4;
    float acc[4][4] = {};
#pragma unroll 8
    for (int t = 0; t < 64; t++) {
        float a0 = As[t][ty * 4 + 0], a1 = As[t][ty * 4 + 1];
        float a2 = As[t][ty * 4 + 2], a3 = As[t][ty * 4 + 3];
        float4 b = *(const float4*)&Bs[t][tx * 4];
        acc[0][0] += a0 * b.x; acc[0][1] += a0 * b.y; acc[0][2] += a0 * b.z; acc[0][3] += a0 * b.w;
        acc[1][0] += a1 * b.x; acc[1][1] += a1 * b.y; acc[1][2] += a1 * b.z; acc[1][3] += a1 * b.w;
        acc[2][0] += a2 * b.x; acc[2][1] += a2 * b.y; acc[2][2] += a2 * b.z; acc[2][3] += a2 * b.w;
        acc[3][0] += a3 * b.x; acc[3][1] += a3 * b.y; acc[3][2] += a3 * b.z; acc[3][3] += a3 * b.w;
    }
#pragma unroll
    for (int r = 0; r < 4; r++) {
        size_t off = (size_t)(i * 64 + ty * 4 + r) * Df + j * 64 + tx * 4;
        float4 old = *(const float4*)&M[off];
        *(float4*)&M[off] = make_float4(old.x - acc[r][0], old.y - acc[r][1],
                                        old.z - acc[r][2], old.w - acc[r][3]);
    }
}

// ---------------- Mahalanobis: triangle + tf32 mma.sync + permuted B ----------------
// A = -Sinv (upper tiles valid). out = 0.7*v - 0.3*||d||^2 where v = d^T A d.
// B tiles staged with column permutation cperm = (c&7)*8 + (c>>3) so each lane's
// four n-fragments are one contiguous float4 (LDS.128 instead of 4 scalar LDS).
__device__ __forceinline__ uint32_t rna_tf32(float f) {
    uint32_t r; asm("cvt.rna.tf32.f32 %0, %1;" : "=r"(r) : "f"(f)); return r;
}
#define DIST_SMEM ((64 * 641 + 2 * 64 * 68 + 128 + 64) * 4)
__global__ void __launch_bounds__(256) k_dist(const float* __restrict__ Xq,
                                              float* __restrict__ out) {
    extern __shared__ __align__(16) float sm[];
    float* Dsm = sm;                     // [64][641] exact fp32 diffs
    float* Bsm = sm + 64 * 641;          // [2][64][68] tf32-rounded, col-permuted tiles
    float* qsum2 = Bsm + 2 * 64 * 68;    // [64][2]
    float* sums = qsum2 + 128;           // [64]
    int c = blockIdx.y, q0 = blockIdx.x * 64, tid = threadIdx.x;
    const float* muc = g_mu + c * Df;
    const float* A = g_sigma + (size_t)c * Df * Df;

    for (int idx = tid; idx < 64 * Df; idx += 256) {
        int q = idx / Df, i = idx - q * Df;
        Dsm[q * 641 + i] = Xq[(size_t)(q0 + q) * Df + i] - muc[i];
    }
    __syncthreads();
    if (tid < 64) {
        const float* dr = Dsm + tid * 641;
        float s = 0.f;
        for (int i = 0; i < Df; i++) { float v = dr[i]; s += v * v; }
        sums[tid] = s;
    }
    __syncthreads();

    int lane = tid & 31, wid = tid >> 5;
    int r4 = lane >> 2, c4 = lane & 3;
    int qrow = (wid & 3) * 16, half = wid >> 2, colhalf = half * 32;
    float dp0 = 0.f, dp1 = 0.f;

    // prefetch first tile (ic=0, jb=0)
    float4 st[4];
#pragma unroll
    for (int t = 0; t < 4; t++) {
        int f4 = tid + 256 * t;
        st[t] = *(const float4*)&A[(size_t)(f4 >> 4) * Df + (f4 & 15) * 4];
    }
    int s = 0;
    for (int jb = 0; jb < 10; jb++) {
        float acc[4][4] = {};
        for (int ic = 0; ic <= jb; ic++, s++) {
            float* buf = Bsm + (s & 1) * (64 * 68);
            // stage: round to tf32 and write with column permutation
#pragma unroll
            for (int t = 0; t < 4; t++) {
                int f4 = tid + 256 * t;
                int row = f4 >> 4, cb = (f4 & 15) * 4;
                float* bp = &buf[row * 68];
                float v[4] = {st[t].x, st[t].y, st[t].z, st[t].w};
#pragma unroll
                for (int u = 0; u < 4; u++) {
                    int cc = cb + u;
                    bp[((cc & 7) << 3) + (cc >> 3)] = __uint_as_float(rna_tf32(v[u]));
                }
            }
            __syncthreads();
            int nic = ic + 1, njb = jb;
            if (nic > jb) { njb = jb + 1; nic = 0; }
            if (njb < 10) {
#pragma unroll
                for (int t = 0; t < 4; t++) {
                    int f4 = tid + 256 * t;
                    st[t] = *(const float4*)&A[(size_t)(nic * 64 + (f4 >> 4)) * Df
                                               + njb * 64 + (f4 & 15) * 4];
                }
            }
            // MMA: G[64q x 64j] += D[:, ic-block] @ buf
            const float* drow0 = Dsm + (qrow + r4) * 641 + ic * 64;
            const float* drow1 = drow0 + 8 * 641;
            const float* bL = buf + r4 * 8 + 4 * half;
#pragma unroll
            for (int k8 = 0; k8 < 8; k8++) {
                int k0 = k8 * 8;
                uint32_t a0 = rna_tf32(drow0[k0 + c4]);
                uint32_t a1 = rna_tf32(drow1[k0 + c4]);
                uint32_t a2 = rna_tf32(drow0[k0 + c4 + 4]);
                uint32_t a3 = rna_tf32(drow1[k0 + c4 + 4]);
                float4 blo = *(const float4*)(bL + (k0 + c4) * 68);
                float4 bhi = *(const float4*)(bL + (k0 + c4 + 4) * 68);
                float bl[4] = {blo.x, blo.y, blo.z, blo.w};
                float bh[4] = {bhi.x, bhi.y, bhi.z, bhi.w};
#pragma unroll
                for (int n = 0; n < 4; n++) {
                    uint32_t b0 = __float_as_uint(bl[n]);
                    uint32_t b1 = __float_as_uint(bh[n]);
                    asm volatile(
                        "mma.sync.aligned.m16n8k8.row.col.f32.tf32.tf32.f32 "
                        "{%0,%1,%2,%3}, {%4,%5,%6,%7}, {%8,%9}, {%0,%1,%2,%3};"
                        : "+f"(acc[n][0]), "+f"(acc[n][1]), "+f"(acc[n][2]), "+f"(acc[n][3])
                        : "r"(a0), "r"(a1), "r"(a2), "r"(a3), "r"(b0), "r"(b1));
                }
            }
            __syncthreads();
            if (ic == jb - 1) {
                const float* dj0 = Dsm + (qrow + r4) * 641 + jb * 64;
                const float* dj1 = dj0 + 8 * 641;
#pragma unroll
                for (int n = 0; n < 4; n++) {
                    int col = colhalf + n * 8 + 2 * c4;
                    dp0 += 2.f * (acc[n][0] * dj0[col] + acc[n][1] * dj0[col + 1]);
                    dp1 += 2.f * (acc[n][2] * dj1[col] + acc[n][3] * dj1[col + 1]);
                    acc[n][0] = acc[n][1] = acc[n][2] = acc[n][3] = 0.f;
                }
            }
        }
        // diagonal tile, weight 1
        const float* dj0 = Dsm + (qrow + r4) * 641 + jb * 64;
        const float* dj1 = dj0 + 8 * 641;
#pragma unroll
        for (int n = 0; n < 4; n++) {
            int col = colhalf + n * 8 + 2 * c4;
            dp0 += acc[n][0] * dj0[col] + acc[n][1] * dj0[col + 1];
            dp1 += acc[n][2] * dj1[col] + acc[n][3] * dj1[col + 1];
        }
    }
    // deterministic butterfly over the 4 lanes sharing a q-row
    dp0 += __shfl_xor_sync(0xffffffffu, dp0, 1);
    dp0 += __shfl_xor_sync(0xffffffffu, dp0, 2);
    dp1 += __shfl_xor_sync(0xffffffffu, dp1, 1);
    dp1 += __shfl_xor_sync(0xffffffffu, dp1, 2);
    if (c4 == 0) {
        qsum2[(qrow + r4) * 2 + half] = dp0;
        qsum2[(qrow + 8 + r4) * 2 + half] = dp1;
    }
    __syncthreads();
    if (tid < 64)
        out[(size_t)(q0 + tid) * Cc + c] =
            0.7f * (qsum2[tid * 2] + qsum2[tid * 2 + 1]) - 0.3f * sums[tid];
}

extern "C" void kernel_launch(void* const* d_in, const int* in_sizes, int n_in,
                              void* d_out, int out_size) {
    const float* X     = (const float*)d_in[0];
    const int*   y     = (const int*)d_in[1];
    const float* Xq    = (const float*)d_in[2];
    const float* m     = (const float*)d_in[3];
    const float* kappa = (const float*)d_in[4];
    const float* nu    = (const float*)d_in[5];
    const float* td    = (const float*)d_in[6];
    const float* tl    = (const float*)d_in[7];
    float* out = (float*)d_out;

    cudaFuncSetAttribute(k_dist, cudaFuncAttributeMaxDynamicSharedMemorySize, DIST_SMEM);

    k_llt<<<dim3(Df / 32, Df / 32), dim3(32, 32)>>>(td, tl);
    k_classidx<<<Cc, 256>>>(y);
    k_mu<<<Cc, 128>>>(X, m, kappa);
    k_sigma<<<dim3(Df / 64, Df / 64, Cc), 256>>>(X, m, kappa, nu);
    for (int kb = 0; kb < NB; kb++) {
        k_savepanel<<<dim3(NB, Cc), 256>>>(kb);
        k_pinv<<<Cc, 256>>>(kb);
        k_rowpanel<<<dim3(NB, Cc), 256>>>(kb);
        k_update<<<dim3(NB, NB, Cc), 256>>>(kb);
    }
    k_dist<<<dim3(Qq / 64, Cc), 256, DIST_SMEM>>>(Xq, out);
}

// round 14
// speedup vs baseline: 1.0889x; 1.0889x over previous
#include <cuda_runtime.h>
#include <cstdint>

#define Df 640
#define Cc 64
#define Nn 1024
#define Qq 2048
#define NB 10
typedef unsigned long long u64t;

__device__ __align__(16) float g_sigma[(size_t)Cc * Df * Df];
__device__ __align__(16) float g_colbuf[(size_t)Cc * NB * 4096];
__device__ __align__(16) float g_rowbuf[(size_t)Cc * NB * 4096];
__device__ __align__(16) float g_pinv[(size_t)Cc * 4096];
__device__ __align__(16) float g_LLt[Df * Df];
__device__ __align__(16) float g_mu[Cc * Df];
__device__ int g_cnt[Cc];
__device__ int g_idx[Cc * Nn];

// ---------------- LLt = L @ L^T (verified) ----------------
__global__ void k_llt(const float* __restrict__ td, const float* __restrict__ tl) {
    __shared__ float Li[32][33], Lj[32][33];
    int i0 = blockIdx.x * 32, j0 = blockIdx.y * 32;
    int tx = threadIdx.x, ty = threadIdx.y;
    float acc = 0.f;
    for (int k0 = 0; k0 < Df; k0 += 32) {
        int k = k0 + tx, r = i0 + ty;
        Li[ty][tx] = (r == k) ? fabsf(td[r]) : ((r > k) ? tl[r * Df + k] : 0.f);
        r = j0 + ty;
        Lj[ty][tx] = (r == k) ? fabsf(td[r]) : ((r > k) ? tl[r * Df + k] : 0.f);
        __syncthreads();
#pragma unroll
        for (int kk = 0; kk < 32; kk++) acc += Li[ty][kk] * Lj[tx][kk];
        __syncthreads();
    }
    g_LLt[(i0 + ty) * Df + (j0 + tx)] = acc;
}

__global__ void k_classidx(const int* __restrict__ y) {
    __shared__ int ys[Nn];
    int c = blockIdx.x;
    for (int n = threadIdx.x; n < Nn; n += blockDim.x) ys[n] = y[n];
    __syncthreads();
    if (threadIdx.x == 0) {
        int cnt = 0;
        for (int n = 0; n < Nn; n++) if (ys[n] == c) g_idx[c * Nn + (cnt++)] = n;
        g_cnt[c] = cnt;
    }
}

__global__ void k_mu(const float* __restrict__ X, const float* __restrict__ m,
                     const float* __restrict__ kappa) {
    int c = blockIdx.x, cnt = g_cnt[c];
    float Nc = (float)cnt, kap = fabsf(kappa[0]) + 1e-6f, w = Nc / (kap + Nc);
    for (int d = threadIdx.x; d < Df; d += blockDim.x) {
        float s = 0.f;
        for (int k = 0; k < cnt; k++) s += X[(size_t)g_idx[c * Nn + k] * Df + d];
        g_mu[c * Df + d] = (1.f - w) * m[d] + w * (s / Nc);
    }
}

// ---------------- sigma build (verified) ----------------
__global__ void __launch_bounds__(256) k_sigma(const float* __restrict__ X,
                                               const float* __restrict__ m,
                                               const float* __restrict__ kappa,
                                               const float* __restrict__ nu) {
    __shared__ float Xi[16][66], Xj[16][66];
    __shared__ int sidx[16];
    int c = blockIdx.z, Ib = blockIdx.y * 64, Jb = blockIdx.x * 64;
    int tid = threadIdx.x, tx = tid & 7, ty = tid >> 3;
    int cnt = g_cnt[c];
    float acc[2][8] = {};
    for (int k0 = 0; k0 < cnt; k0 += 16) {
        int nl = min(16, cnt - k0);
        if (tid < 16) sidx[tid] = (tid < nl) ? g_idx[c * Nn + k0 + tid] : 0;
        __syncthreads();
        for (int idx = tid; idx < 16 * 64; idx += 256) {
            int s = idx >> 6, col = idx & 63;
            float vi = 0.f, vj = 0.f;
            if (s < nl) {
                const float* xr = X + (size_t)sidx[s] * Df;
                vi = xr[Ib + col]; vj = xr[Jb + col];
            }
            Xi[s][col] = vi; Xj[s][col] = vj;
        }
        __syncthreads();
#pragma unroll
        for (int t = 0; t < 16; t++) {
            float a0 = Xi[t][ty * 2], a1 = Xi[t][ty * 2 + 1];
            const float* bj = &Xj[t][tx * 8];
#pragma unroll
            for (int k = 0; k < 8; k++) {
                float b = bj[k];
                acc[0][k] += a0 * b;
                acc[1][k] += a1 * b;
            }
        }
        __syncthreads();
    }
    float kap = fabsf(kappa[0]) + 1e-6f;
    float nu_ = fmaxf(nu[0], (float)(Df - 1) + 1e-6f);
    float Nc = (float)cnt;
    float inv_denom = 1.f / (nu_ + Nc + (float)Df + 2.f);
    float kpn = kap + Nc;
#pragma unroll
    for (int r = 0; r < 2; r++) {
        int i = Ib + ty * 2 + r;
        float mi = m[i], mui = g_mu[c * Df + i];
        float* dst = g_sigma + (size_t)c * Df * Df + (size_t)i * Df + Jb + tx * 8;
        const float* llt = g_LLt + (size_t)i * Df + Jb + tx * 8;
#pragma unroll
        for (int k = 0; k < 8; k++) {
            int j = Jb + tx * 8 + k;
            float v = llt[k] + acc[r][k] + kap * mi * m[j] - kpn * mui * g_mu[c * Df + j];
            dst[k] = v * inv_denom;
        }
    }
}

// ---------------- sweep steps A+B merged: save panels / invert pivot ----------------
// grid (NB, Cc): block b==kb inverts the pivot block; other blocks save A[K,b].
// Both only READ the pre-step matrix, so they are safely parallel.
__global__ void __launch_bounds__(256) k_pinvsave(int kb) {
    __shared__ float Ssm[64 * 65 + 64];
    int b = blockIdx.x, c = blockIdx.y, tid = threadIdx.x, K0 = kb * 64;
    const float* M = g_sigma + (size_t)c * Df * Df;
    if (b != kb) {
        float* dst = g_colbuf + ((size_t)c * NB + b) * 4096;
        if (b > kb) {
            for (int idx = tid; idx < 4096; idx += 256) {
                int t = idx >> 6, a = idx & 63;
                dst[idx] = M[(size_t)(K0 + t) * Df + b * 64 + a];
            }
        } else {
            float* Ts = Ssm;  // [64][65]
            for (int idx = tid; idx < 4096; idx += 256) {
                int a = idx >> 6, t = idx & 63;
                Ts[a * 65 + t] = M[(size_t)(b * 64 + a) * Df + K0 + t];
            }
            __syncthreads();
            for (int idx = tid; idx < 4096; idx += 256) {
                int t = idx >> 6, a = idx & 63;
                dst[idx] = Ts[a * 65 + t];
            }
        }
        return;
    }
    float* Psm = Ssm;
    float* colv = Ssm + 64 * 65;
    for (int idx = tid; idx < 4096; idx += 256)
        Psm[(idx >> 6) * 65 + (idx & 63)] = M[(size_t)(K0 + (idx >> 6)) * Df + K0 + (idx & 63)];
    __syncthreads();
    for (int t = 0; t < 64; t++) {
        if (tid < 64) colv[tid] = Psm[tid * 65 + t];
        __syncthreads();
        float invp = 1.f / colv[t];
        if (tid < 64) {
            float v = Psm[t * 65 + tid];
            Psm[t * 65 + tid] = (tid == t) ? invp : v * invp;
        }
        __syncthreads();
        for (int idx = tid; idx < 4096; idx += 256) {
            int i = idx >> 6, j = idx & 63;
            if (i != t) {
                float base = (j == t) ? 0.f : Psm[i * 65 + j];
                Psm[i * 65 + j] = base - colv[i] * Psm[t * 65 + j];
            }
        }
        __syncthreads();
    }
    for (int idx = tid; idx < 4096; idx += 256)
        g_pinv[(size_t)c * 4096 + idx] = Psm[(idx >> 6) * 65 + (idx & 63)];
}

// ---------------- sweep step C: rowpanel (verified R10) ----------------
__global__ void __launch_bounds__(256) k_rowpanel(int kb) {
    int j = blockIdx.x, c = blockIdx.y;
    int tid = threadIdx.x, K0 = kb * 64;
    float* M = g_sigma + (size_t)c * Df * Df;
    const float* Pv = g_pinv + (size_t)c * 4096;
    if (j == kb) {
        for (int idx = tid; idx < 4096; idx += 256)
            M[(size_t)(K0 + (idx >> 6)) * Df + K0 + (idx & 63)] = -Pv[idx];
        return;
    }
    __shared__ float Ps[64][65];
    __shared__ __align__(16) float Rs[64][68];
    for (int idx = tid; idx < 4096; idx += 256) {
        Ps[idx >> 6][idx & 63] = Pv[idx];
        Rs[idx >> 6][idx & 63] = g_colbuf[((size_t)c * NB + j) * 4096 + idx];
    }
    __syncthreads();
    int tx = tid & 15, ty = tid >> 4;
    float acc[4][4] = {};
#pragma unroll 8
    for (int t = 0; t < 64; t++) {
        float a0 = Ps[ty * 4 + 0][t], a1 = Ps[ty * 4 + 1][t];
        float a2 = Ps[ty * 4 + 2][t], a3 = Ps[ty * 4 + 3][t];
        float4 b = *(const float4*)&Rs[t][tx * 4];
        acc[0][0] += a0 * b.x; acc[0][1] += a0 * b.y; acc[0][2] += a0 * b.z; acc[0][3] += a0 * b.w;
        acc[1][0] += a1 * b.x; acc[1][1] += a1 * b.y; acc[1][2] += a1 * b.z; acc[1][3] += a1 * b.w;
        acc[2][0] += a2 * b.x; acc[2][1] += a2 * b.y; acc[2][2] += a2 * b.z; acc[2][3] += a2 * b.w;
        acc[3][0] += a3 * b.x; acc[3][1] += a3 * b.y; acc[3][2] += a3 * b.z; acc[3][3] += a3 * b.w;
    }
    float* rb = g_rowbuf + ((size_t)c * NB + j) * 4096;
#pragma unroll
    for (int r = 0; r < 4; r++)
        *(float4*)&rb[(ty * 4 + r) * 64 + tx * 4] =
            make_float4(acc[r][0], acc[r][1], acc[r][2], acc[r][3]);
    if (j > kb) {
#pragma unroll
        for (int r = 0; r < 4; r++)
            *(float4*)&M[(size_t)(K0 + ty * 4 + r) * Df + j * 64 + tx * 4] =
                make_float4(acc[r][0], acc[r][1], acc[r][2], acc[r][3]);
    } else {
        __syncthreads();
#pragma unroll
        for (int r = 0; r < 4; r++) {
            Ps[ty * 4 + r][tx * 4 + 0] = acc[r][0];
            Ps[ty * 4 + r][tx * 4 + 1] = acc[r][1];
            Ps[ty * 4 + r][tx * 4 + 2] = acc[r][2];
            Ps[ty * 4 + r][tx * 4 + 3] = acc[r][3];
        }
        __syncthreads();
        for (int idx = tid; idx < 4096; idx += 256) {
            int x = idx >> 6, yv = idx & 63;
            M[(size_t)(j * 64 + x) * Df + K0 + yv] = Ps[yv][x];
        }
    }
}

// ---------------- sweep step D: rank-64 update upper tiles (verified R10) ----------------
__global__ void __launch_bounds__(256) k_update(int kb) {
    int j = blockIdx.x, i = blockIdx.y, c = blockIdx.z;
    if (i > j || i == kb || j == kb) return;
    __shared__ float As[64][65];
    __shared__ __align__(16) float Bs[64][68];
    int tid = threadIdx.x;
    const float* ca = g_colbuf + ((size_t)c * NB + i) * 4096;
    const float* rb = g_rowbuf + ((size_t)c * NB + j) * 4096;
    for (int idx = tid; idx < 4096; idx += 256) {
        As[idx >> 6][idx & 63] = ca[idx];
        Bs[idx >> 6][idx & 63] = rb[idx];
    }
    __syncthreads();
    float* M = g_sigma + (size_t)c * Df * Df;
    int tx = tid & 15, ty = tid >> 4;
    float acc[4][4] = {};
#pragma unroll 8
    for (int t = 0; t < 64; t++) {
        float a0 = As[t][ty * 4 + 0], a1 = As[t][ty * 4 + 1];
        float a2 = As[t][ty * 4 + 2], a3 = As[t][ty * 4 + 3];
        float4 b = *(const float4*)&Bs[t][tx * 4];
        acc[0][0] += a0 * b.x; acc[0][1] += a0 * b.y; acc[0][2] += a0 * b.z; acc[0][3] += a0 * b.w;
        acc[1][0] += a1 * b.x; acc[1][1] += a1 * b.y; acc[1][2] += a1 * b.z; acc[1][3] += a1 * b.w;
        acc[2][0] += a2 * b.x; acc[2][1] += a2 * b.y; acc[2][2] += a2 * b.z; acc[2][3] += a2 * b.w;
        acc[3][0] += a3 * b.x; acc[3][1] += a3 * b.y; acc[3][2] += a3 * b.z; acc[3][3] += a3 * b.w;
    }
#pragma unroll
    for (int r = 0; r < 4; r++) {
        size_t off = (size_t)(i * 64 + ty * 4 + r) * Df + j * 64 + tx * 4;
        float4 old = *(const float4*)&M[off];
        *(float4*)&M[off] = make_float4(old.x - acc[r][0], old.y - acc[r][1],
                                        old.z - acc[r][2], old.w - acc[r][3]);
    }
}

// ---------------- Mahalanobis: triangle + tf32 mma.sync (R12 exact, minus post-MMA sync) ----------------
// A = -Sinv (upper tiles valid). out = 0.7*v - 0.3*||d||^2 where v = d^T A d.
// Double-buffered B tiles: the barrier after staging tile s+1 already orders all
// warps past mma(s), so the post-MMA barrier is redundant — removed to let
// staging(s+1) overlap mma(s) across warps.
__device__ __forceinline__ uint32_t rna_tf32(float f) {
    uint32_t r; asm("cvt.rna.tf32.f32 %0, %1;" : "=r"(r) : "f"(f)); return r;
}
#define DIST_SMEM ((64 * 641 + 2 * 64 * 72 + 128 + 64) * 4)
__global__ void __launch_bounds__(256) k_dist(const float* __restrict__ Xq,
                                              float* __restrict__ out) {
    extern __shared__ __align__(16) float sm[];
    float* Dsm = sm;                     // [64][641] exact fp32 diffs
    float* Bsm = sm + 64 * 641;          // [2][64][72] tf32-rounded S tiles
    float* qsum2 = Bsm + 2 * 64 * 72;    // [64][2]
    float* sums = qsum2 + 128;           // [64]
    int c = blockIdx.y, q0 = blockIdx.x * 64, tid = threadIdx.x;
    const float* muc = g_mu + c * Df;
    const float* A = g_sigma + (size_t)c * Df * Df;

    for (int idx = tid; idx < 64 * Df; idx += 256) {
        int q = idx / Df, i = idx - q * Df;
        Dsm[q * 641 + i] = Xq[(size_t)(q0 + q) * Df + i] - muc[i];
    }
    __syncthreads();
    if (tid < 64) {
        const float* dr = Dsm + tid * 641;
        float s = 0.f;
        for (int i = 0; i < Df; i++) { float v = dr[i]; s += v * v; }
        sums[tid] = s;
    }
    __syncthreads();

    int lane = tid & 31, wid = tid >> 5;
    int r4 = lane >> 2, c4 = lane & 3;
    int qrow = (wid & 3) * 16, half = wid >> 2, colhalf = half * 32;
    float dp0 = 0.f, dp1 = 0.f;

    // prefetch first tile (ic=0, jb=0)
    float4 st[4];
#pragma unroll
    for (int t = 0; t < 4; t++) {
        int f4 = tid + 256 * t;
        st[t] = *(const float4*)&A[(size_t)(f4 >> 4) * Df + (f4 & 15) * 4];
    }
    int s = 0;
    for (int jb = 0; jb < 10; jb++) {
        float acc[4][4] = {};
        for (int ic = 0; ic <= jb; ic++, s++) {
            float* buf = Bsm + (s & 1) * (64 * 72);
#pragma unroll
            for (int t = 0; t < 4; t++) {
                int f4 = tid + 256 * t;
                float* bp = &buf[(f4 >> 4) * 72 + (f4 & 15) * 4];
                bp[0] = __uint_as_float(rna_tf32(st[t].x));
                bp[1] = __uint_as_float(rna_tf32(st[t].y));
                bp[2] = __uint_as_float(rna_tf32(st[t].z));
                bp[3] = __uint_as_float(rna_tf32(st[t].w));
            }
            __syncthreads();
            int nic = ic + 1, njb = jb;
            if (nic > jb) { njb = jb + 1; nic = 0; }
            if (njb < 10) {
#pragma unroll
                for (int t = 0; t < 4; t++) {
                    int f4 = tid + 256 * t;
                    st[t] = *(const float4*)&A[(size_t)(nic * 64 + (f4 >> 4)) * Df
                                               + njb * 64 + (f4 & 15) * 4];
                }
            }
            // MMA: G[64q x 64j] += D[:, ic-block] @ buf
            const float* drow0 = Dsm + (qrow + r4) * 641 + ic * 64;
            const float* drow1 = drow0 + 8 * 641;
#pragma unroll
            for (int k8 = 0; k8 < 8; k8++) {
                int k0 = k8 * 8;
                uint32_t a0 = rna_tf32(drow0[k0 + c4]);
                uint32_t a1 = rna_tf32(drow1[k0 + c4]);
                uint32_t a2 = rna_tf32(drow0[k0 + c4 + 4]);
                uint32_t a3 = rna_tf32(drow1[k0 + c4 + 4]);
                const float* b0p = buf + (k0 + c4) * 72 + colhalf + r4;
                const float* b1p = b0p + 4 * 72;
#pragma unroll
                for (int n = 0; n < 4; n++) {
                    uint32_t b0 = __float_as_uint(b0p[n * 8]);
                    uint32_t b1 = __float_as_uint(b1p[n * 8]);
                    asm volatile(
                        "mma.sync.aligned.m16n8k8.row.col.f32.tf32.tf32.f32 "
                        "{%0,%1,%2,%3}, {%4,%5,%6,%7}, {%8,%9}, {%0,%1,%2,%3};"
                        : "+f"(acc[n][0]), "+f"(acc[n][1]), "+f"(acc[n][2]), "+f"(acc[n][3])
                        : "r"(a0), "r"(a1), "r"(a2), "r"(a3), "r"(b0), "r"(b1));
                }
            }
            // NOTE: no post-MMA __syncthreads() — double buffering makes it redundant.
            if (ic == jb - 1) {
                const float* dj0 = Dsm + (qrow + r4) * 641 + jb * 64;
                const float* dj1 = dj0 + 8 * 641;
#pragma unroll
                for (int n = 0; n < 4; n++) {
                    int col = colhalf + n * 8 + 2 * c4;
                    dp0 += 2.f * (acc[n][0] * dj0[col] + acc[n][1] * dj0[col + 1]);
                    dp1 += 2.f * (acc[n][2] * dj1[col] + acc[n][3] * dj1[col + 1]);
                    acc[n][0] = acc[n][1] = acc[n][2] = acc[n][3] = 0.f;
                }
            }
        }
        // diagonal tile, weight 1
        const float* dj0 = Dsm + (qrow + r4) * 641 + jb * 64;
        const float* dj1 = dj0 + 8 * 641;
#pragma unroll
        for (int n = 0; n < 4; n++) {
            int col = colhalf + n * 8 + 2 * c4;
            dp0 += acc[n][0] * dj0[col] + acc[n][1] * dj0[col + 1];
            dp1 += acc[n][2] * dj1[col] + acc[n][3] * dj1[col + 1];
        }
    }
    // deterministic butterfly over the 4 lanes sharing a q-row
    dp0 += __shfl_xor_sync(0xffffffffu, dp0, 1);
    dp0 += __shfl_xor_sync(0xffffffffu, dp0, 2);
    dp1 += __shfl_xor_sync(0xffffffffu, dp1, 1);
    dp1 += __shfl_xor_sync(0xffffffffu, dp1, 2);
    if (c4 == 0) {
        qsum2[(qrow + r4) * 2 + half] = dp0;
        qsum2[(qrow + 8 + r4) * 2 + half] = dp1;
    }
    __syncthreads();
    if (tid < 64)
        out[(size_t)(q0 + tid) * Cc + c] =
            0.7f * (qsum2[tid * 2] + qsum2[tid * 2 + 1]) - 0.3f * sums[tid];
}

extern "C" void kernel_launch(void* const* d_in, const int* in_sizes, int n_in,
                              void* d_out, int out_size) {
    const float* X     = (const float*)d_in[0];
    const int*   y     = (const int*)d_in[1];
    const float* Xq    = (const float*)d_in[2];
    const float* m     = (const float*)d_in[3];
    const float* kappa = (const float*)d_in[4];
    const float* nu    = (const float*)d_in[5];
    const float* td    = (const float*)d_in[6];
    const float* tl    = (const float*)d_in[7];
    float* out = (float*)d_out;

    cudaFuncSetAttribute(k_dist, cudaFuncAttributeMaxDynamicSharedMemorySize, DIST_SMEM);

    k_llt<<<dim3(Df / 32, Df / 32), dim3(32, 32)>>>(td, tl);
    k_classidx<<<Cc, 256>>>(y);
    k_mu<<<Cc, 128>>>(X, m, kappa);
    k_sigma<<<dim3(Df / 64, Df / 64, Cc), 256>>>(X, m, kappa, nu);
    for (int kb = 0; kb < NB; kb++) {
        k_pinvsave<<<dim3(NB, Cc), 256>>>(kb);
        k_rowpanel<<<dim3(NB, Cc), 256>>>(kb);
        k_update<<<dim3(NB, NB, Cc), 256>>>(kb);
    }
    k_dist<<<dim3(Qq / 64, Cc), 256, DIST_SMEM>>>(Xq, out);
}